// round 7
// baseline (speedup 1.0000x reference)
#include <cuda_runtime.h>
#include <math.h>

#define LSEQ 1024
#define NDIM 256

// Output layout (floats): c_all, y_all, GBT_A, GBT_B
#define OFF_Y    (LSEQ * NDIM)
#define OFF_GBTA (LSEQ * NDIM + LSEQ)
#define OFF_GBTB (LSEQ * NDIM + LSEQ + LSEQ * NDIM * NDIM)

// Writer tables (unchanged from passing R5 kernel)
__device__ float g_rowv[LSEQ * NDIM];
__device__ float g_colv[LSEQ * NDIM];
__device__ float g_xd  [LSEQ * NDIM];
__device__ int   g_Ei  [LSEQ * NDIM];
__device__ int   g_Ej  [LSEQ * NDIM];

// Scan constant tables: per step k, 9 float4s per lane, [k][j][lane] for
// coalesced LDG.128. j: 0-1 rho[0..7], 2-3 g[0..7], 4-5 Ghat[0..7] (=suffix
// prod of g * r), 6 Aa[0..3], 7 (Aa4,Aa5,Aa6,K4), 8 (K0..K3).
__device__ float4 g_tab[LSEQ][9][32];

__device__ __forceinline__ float pow2i(int n) {
    return (n < -126) ? 0.0f : __int_as_float((n + 127) << 23);
}

__device__ __forceinline__ float f4c(float4 v, int e) {
    return e == 0 ? v.x : e == 1 ? v.y : e == 2 ? v.z : v.w;
}

// ---------------------------------------------------------------------------
// Kernel 1: writer tables (validated) + scan constant tables.
// ---------------------------------------------------------------------------
__global__ void params_kernel(float* __restrict__ gbtb)
{
    int k = blockIdx.x;          // step = k+1
    int j = threadIdx.x;         // 0..255
    float ss = 1.0f / (float)(k + 1);
    float hh = 0.5f * ss;
    float rj = sqrtf(2.0f * (float)j + 1.0f);
    float d  = fmaf(hh, (float)(j + 1), 1.0f);
    float invd = 1.0f / d;
    float graw = fmaf(-hh, (float)j, 1.0f) * invd;   // exact g (scan)
    float g = (graw == 0.0f) ? 1e-30f : graw;        // writer-safe g

    __shared__ float sm[NDIM];
    __shared__ int   se[NDIM];
    __shared__ float sgs[NDIM];
    __shared__ float srho[NDIM];
    sgs[j]  = graw;
    srho[j] = rj * invd;

    int e; float m = frexpf(g, &e);
    sm[j] = m; se[j] = e;
    __syncthreads();
    #pragma unroll
    for (int off = 1; off < NDIM; off <<= 1) {
        float pm = 0.0f; int pe = 0;
        bool act = (j >= off);
        if (act) { pm = sm[j - off]; pe = se[j - off]; }
        __syncthreads();
        if (act) {
            m = m * pm; e = e + pe;
            if (fabsf(m) < 0.5f) { m *= 2.0f; e -= 1; }
            sm[j] = m; se[j] = e;
        }
        __syncthreads();
    }
    float Mj = m; int Ej = e;
    float Mi = 1.0f; int Ei = 0;
    if (j > 0) { Mi = sm[j - 1]; Ei = se[j - 1]; }

    float rd  = rj * invd;
    int   idx = k * NDIM + j;
    g_rowv[idx] = -2.0f * hh * rd * Mi;
    g_colv[idx] = rd / Mj;
    g_xd[idx]   = fmaf(-hh, (float)(j + 1), 1.0f) * invd;
    g_Ei[idx]   = Ei;
    g_Ej[idx]   = Ej;
    gbtb[idx]   = ss * rd * Mi * pow2i(Ei);

    // ------------------ scan tables (warp 0, lane l = j) -------------------
    if (j < 32) {
        int l = j;
        float ge[8], rhoe[8];
        #pragma unroll
        for (int t = 0; t < 8; t++) { ge[t] = sgs[8 * l + t]; rhoe[t] = srho[8 * l + t]; }
        float Aa[7];
        Aa[0] = ge[0];
        #pragma unroll
        for (int t = 1; t < 7; t++) Aa[t] = Aa[t - 1] * ge[t];
        float Atot = Aa[6] * ge[7];
        float Gs[8];
        Gs[7] = 1.0f;
        #pragma unroll
        for (int t = 6; t >= 0; t--) Gs[t] = Gs[t + 1] * ge[t + 1];
        // Ghat = Gs * r
        float Gh[8];
        #pragma unroll
        for (int t = 0; t < 8; t++) Gh[t] = Gs[t] * sqrtf(2.0f * (float)(8 * l + t) + 1.0f);
        // Kogge-Stone A coefficients
        float A = Atot, Ao;
        float K0 = A, K1, K2, K3, K4;
        Ao = __shfl_up_sync(0xffffffffu, A, 1);  if (l >= 1) A *= Ao; K1 = A;
        Ao = __shfl_up_sync(0xffffffffu, A, 2);  if (l >= 2) A *= Ao; K2 = A;
        Ao = __shfl_up_sync(0xffffffffu, A, 4);  if (l >= 4) A *= Ao; K3 = A;
        Ao = __shfl_up_sync(0xffffffffu, A, 8);  if (l >= 8) A *= Ao; K4 = A;

        g_tab[k][0][l] = make_float4(rhoe[0], rhoe[1], rhoe[2], rhoe[3]);
        g_tab[k][1][l] = make_float4(rhoe[4], rhoe[5], rhoe[6], rhoe[7]);
        g_tab[k][2][l] = make_float4(ge[0], ge[1], ge[2], ge[3]);
        g_tab[k][3][l] = make_float4(ge[4], ge[5], ge[6], ge[7]);
        g_tab[k][4][l] = make_float4(Gh[0], Gh[1], Gh[2], Gh[3]);
        g_tab[k][5][l] = make_float4(Gh[4], Gh[5], Gh[6], Gh[7]);
        g_tab[k][6][l] = make_float4(Aa[0], Aa[1], Aa[2], Aa[3]);
        g_tab[k][7][l] = make_float4(Aa[4], Aa[5], Aa[6], K4);
        g_tab[k][8][l] = make_float4(K0, K1, K2, K3);
    }
}

// One scan step. CUR/NXT are float4[9] register arrays (constant-indexed).
// Uses HHc/SFc; prefetches table for step (kk+1) into NXT; computes HHn/SFn.
#define SCAN_STEP(CUR, NXT, kk, HHc, SFc, HHn, SFn)                           \
do {                                                                          \
    int kt = ((kk) < LSEQ) ? (kk) : (LSEQ - 1);                               \
    _Pragma("unroll")                                                         \
    for (int jj = 0; jj < 9; jj++) NXT[jj] = g_tab[kt][jj][lane];             \
    float ssn = 1.0f / (float)((kk) + 1);                                     \
    HHn = 0.5f * ssn;                                                         \
    SFn = ssn * shf[kt];                                                      \
    float rho[8], gg[8], Gh[8];                                               \
    _Pragma("unroll")                                                         \
    for (int e = 0; e < 8; e++) {                                             \
        rho[e] = f4c(CUR[e >> 2], e & 3);                                     \
        gg[e]  = f4c(CUR[2 + (e >> 2)], e & 3);                               \
        Gh[e]  = f4c(CUR[4 + (e >> 2)], e & 3);                               \
    }                                                                         \
    float Aa[7] = {CUR[6].x, CUR[6].y, CUR[6].z, CUR[6].w,                    \
                   CUR[7].x, CUR[7].y, CUR[7].z};                             \
    float K0 = CUR[8].x, K1 = CUR[8].y, K2 = CUR[8].z, K3 = CUR[8].w;         \
    float K4 = CUR[7].w;                                                      \
    float wt[8], uu[8];                                                       \
    _Pragma("unroll")                                                         \
    for (int e = 0; e < 8; e++) {                                             \
        float t1 = fmaf(-(HHc), Sx[e], (SFc));                                \
        float t3 = fmaf(tri[e] * cc[e], rho[e], -cc[e]);                      \
        wt[e] = fmaf(rho[e], t1, t3);                                         \
        uu[e] = rr[e] * wt[e];                                                \
    }                                                                         \
    float Bt = ((Gh[0]*wt[0] + Gh[1]*wt[1]) + (Gh[2]*wt[2] + Gh[3]*wt[3]))    \
             + ((Gh[4]*wt[4] + Gh[5]*wt[5]) + (Gh[6]*wt[6] + Gh[7]*wt[7]));   \
    float Bb[7];                                                              \
    Bb[0] = uu[0];                                                            \
    _Pragma("unroll")                                                         \
    for (int e = 1; e < 7; e++) Bb[e] = fmaf(gg[e], Bb[e - 1], uu[e]);        \
    float Bs = Bt, Bo;                                                        \
    Bo = __shfl_up_sync(0xffffffffu, Bs, 1);  if (lane >= 1)  Bs = fmaf(K0, Bo, Bs); \
    Bo = __shfl_up_sync(0xffffffffu, Bs, 2);  if (lane >= 2)  Bs = fmaf(K1, Bo, Bs); \
    Bo = __shfl_up_sync(0xffffffffu, Bs, 4);  if (lane >= 4)  Bs = fmaf(K2, Bo, Bs); \
    Bo = __shfl_up_sync(0xffffffffu, Bs, 8);  if (lane >= 8)  Bs = fmaf(K3, Bo, Bs); \
    Bo = __shfl_up_sync(0xffffffffu, Bs, 16); if (lane >= 16) Bs = fmaf(K4, Bo, Bs); \
    float V = __shfl_up_sync(0xffffffffu, Bs, 1);                             \
    if (lane == 0) V = 0.0f;                                                  \
    Sx[0] = V;                                                                \
    cc[0] = fmaf(-(HHc), rho[0] * V, wt[0]);                                  \
    _Pragma("unroll")                                                         \
    for (int e = 1; e < 8; e++) {                                             \
        float Sn = fmaf(Aa[e - 1], V, Bb[e - 1]);                             \
        cc[e] = fmaf(-(HHc), rho[e] * Sn, wt[e]);                             \
        Sx[e] = Sn;                                                           \
    }                                                                         \
    cptr[0] = make_float4(cc[0], cc[1], cc[2], cc[3]);                        \
    cptr[1] = make_float4(cc[4], cc[5], cc[6], cc[7]);                        \
    cptr += NDIM / 4;                                                         \
} while (0)

// ---------------------------------------------------------------------------
// Kernel 2 (fused): block 0 = sequential scan, blocks 1.. = GBT_A writer.
// ---------------------------------------------------------------------------
__global__ void __launch_bounds__(256) fused_kernel(
    const float* __restrict__ f,
    const float* __restrict__ init_state,
    float* __restrict__ out)
{
    if (blockIdx.x != 0) {
        // ----------------- GBT_A writer (unchanged, validated) -------------
        int wb = blockIdx.x - 1;
        int k  = wb >> 3;
        int i0 = (wb & 7) * 32;
        int tx = threadIdx.x & 63;
        int ty = threadIdx.x >> 6;
        int jb = tx * 4;
        const float4 cv = *reinterpret_cast<const float4*>(&g_colv[k * NDIM + jb]);
        const int4   ev = *reinterpret_cast<const int4*>  (&g_Ej  [k * NDIM + jb]);
        float* base = out + (size_t)OFF_GBTA + (size_t)k * (NDIM * NDIM);
        #pragma unroll
        for (int rr = 0; rr < 8; rr++) {
            int i = i0 + ty + rr * 4;
            float rv = g_rowv[k * NDIM + i];
            int   Ei = g_Ei  [k * NDIM + i];
            float xd = g_xd  [k * NDIM + i];
            float4 o;
            o.x = (jb + 0 > i) ? 0.0f : ((jb + 0 == i) ? xd : rv * cv.x * pow2i(Ei - ev.x));
            o.y = (jb + 1 > i) ? 0.0f : ((jb + 1 == i) ? xd : rv * cv.y * pow2i(Ei - ev.y));
            o.z = (jb + 2 > i) ? 0.0f : ((jb + 2 == i) ? xd : rv * cv.z * pow2i(Ei - ev.z));
            o.w = (jb + 3 > i) ? 0.0f : ((jb + 3 == i) ? xd : rv * cv.w * pow2i(Ei - ev.w));
            *reinterpret_cast<float4*>(&base[(size_t)i * NDIM + jb]) = o;
        }
        return;
    }

    // --------------------- scan block: single warp, 8 elems/lane ----------
    __shared__ float shf[LSEQ];
    for (int t = threadIdx.x; t < LSEQ; t += 256) shf[t] = f[t];
    __syncthreads();
    if (threadIdx.x >= 32) return;
    int lane = threadIdx.x;

    float rr[8], tri[8], cc[8], Sx[8];
    #pragma unroll
    for (int e = 0; e < 8; e++) {
        int i  = lane * 8 + e;
        rr[e]  = sqrtf(2.0f * (float)i + 1.0f);
        tri[e] = 2.0f / rr[e];
        cc[e]  = init_state[i];
    }
    // Initial exclusive prefix of r_j * c_j
    {
        float lex[8]; float run = 0.0f;
        #pragma unroll
        for (int e = 0; e < 8; e++) { lex[e] = run; run = fmaf(rr[e], cc[e], run); }
        float tot = run;
        #pragma unroll
        for (int off = 1; off < 32; off <<= 1) {
            float v = __shfl_up_sync(0xffffffffu, tot, off);
            if (lane >= off) tot += v;
        }
        float carry = __shfl_up_sync(0xffffffffu, tot, 1);
        if (lane == 0) carry = 0.0f;
        #pragma unroll
        for (int e = 0; e < 8; e++) Sx[e] = carry + lex[e];
    }

    float4* cptr = reinterpret_cast<float4*>(out) + lane * 2;

    // Preload step-1 constants + scalars
    float4 bufA[9], bufB[9];
    #pragma unroll
    for (int jj = 0; jj < 9; jj++) bufA[jj] = g_tab[0][jj][lane];
    float hhA = 0.5f, sfA = shf[0];   // step 1: ss = 1
    float hhB, sfB;

    #pragma unroll 1
    for (int k = 1; k <= LSEQ; k += 2) {
        SCAN_STEP(bufA, bufB, k,     hhA, sfA, hhB, sfB);
        SCAN_STEP(bufB, bufA, k + 1, hhB, sfB, hhA, sfA);
    }
}

// ---------------------------------------------------------------------------
// Kernel 3: y_all[k] = sum_i c_all[k][i]  (off the scan's critical loop)
// ---------------------------------------------------------------------------
__global__ void y_kernel(const float* __restrict__ c_all, float* __restrict__ y_all)
{
    int row  = blockIdx.x * 8 + (threadIdx.x >> 5);
    int lane = threadIdx.x & 31;
    const float4* p = reinterpret_cast<const float4*>(c_all + (size_t)row * NDIM);
    float4 a = p[lane * 2], b = p[lane * 2 + 1];
    float s = ((a.x + a.y) + (a.z + a.w)) + ((b.x + b.y) + (b.z + b.w));
    #pragma unroll
    for (int off = 16; off >= 1; off >>= 1)
        s += __shfl_down_sync(0xffffffffu, s, off);
    if (lane == 0) y_all[row] = s;
}

extern "C" void kernel_launch(void* const* d_in, const int* in_sizes, int n_in,
                              void* d_out, int out_size)
{
    int fi = 0, ii = 1;
    if (n_in >= 4 && in_sizes[0] == NDIM * NDIM) { fi = 2; ii = 3; }
    const float* f    = (const float*)d_in[fi];
    const float* init = (const float*)d_in[ii];
    float* out = (float*)d_out;

    params_kernel<<<LSEQ, NDIM>>>(out + (size_t)OFF_GBTB);
    fused_kernel<<<1 + LSEQ * 8, 256>>>(f, init, out);
    y_kernel<<<LSEQ / 8, 256>>>(out, out + (size_t)OFF_Y);
}

// round 8
// speedup vs baseline: 3.8321x; 3.8321x over previous
#include <cuda_runtime.h>
#include <math.h>

#define LSEQ 1024
#define NDIM 256

// Output layout (floats): c_all, y_all, GBT_A, GBT_B
#define OFF_Y    (LSEQ * NDIM)
#define OFF_GBTA (LSEQ * NDIM + LSEQ)
#define OFF_GBTB (LSEQ * NDIM + LSEQ + LSEQ * NDIM * NDIM)

// Writer tables (validated in R5)
__device__ float g_rowv[LSEQ * NDIM];
__device__ float g_colv[LSEQ * NDIM];
__device__ float g_xd  [LSEQ * NDIM];
__device__ int   g_Ei  [LSEQ * NDIM];
__device__ int   g_Ej  [LSEQ * NDIM];

__device__ __forceinline__ float pow2i(int n) {
    return (n < -126) ? 0.0f : __int_as_float((n + 127) << 23);
}

// ---------------------------------------------------------------------------
// Kernel 1: writer factor tables + GBT_B (identical to validated R5 version).
// ---------------------------------------------------------------------------
__global__ void params_kernel(float* __restrict__ gbtb)
{
    int k = blockIdx.x;          // step = k+1
    int j = threadIdx.x;         // 0..255
    float ss = 1.0f / (float)(k + 1);
    float hh = 0.5f * ss;
    float rj = sqrtf(2.0f * (float)j + 1.0f);
    float d  = fmaf(hh, (float)(j + 1), 1.0f);
    float invd = 1.0f / d;
    float g = fmaf(-hh, (float)j, 1.0f) * invd;
    if (g == 0.0f) g = 1e-30f;

    int e; float m = frexpf(g, &e);
    __shared__ float sm[NDIM];
    __shared__ int   se[NDIM];
    sm[j] = m; se[j] = e;
    __syncthreads();
    #pragma unroll
    for (int off = 1; off < NDIM; off <<= 1) {
        float pm = 0.0f; int pe = 0;
        bool act = (j >= off);
        if (act) { pm = sm[j - off]; pe = se[j - off]; }
        __syncthreads();
        if (act) {
            m = m * pm; e = e + pe;
            if (fabsf(m) < 0.5f) { m *= 2.0f; e -= 1; }
            sm[j] = m; se[j] = e;
        }
        __syncthreads();
    }
    float Mj = m; int Ej = e;
    float Mi = 1.0f; int Ei = 0;
    if (j > 0) { Mi = sm[j - 1]; Ei = se[j - 1]; }

    float rd  = rj * invd;
    int   idx = k * NDIM + j;
    g_rowv[idx] = -2.0f * hh * rd * Mi;
    g_colv[idx] = rd / Mj;
    g_xd[idx]   = fmaf(-hh, (float)(j + 1), 1.0f) * invd;
    g_Ei[idx]   = Ei;
    g_Ej[idx]   = Ej;
    gbtb[idx]   = ss * rd * Mi * pow2i(Ei);
}

// Reciprocal table in smem: rtab[pm(m)] = 1/m, pm(m) = m + (m>>3)
// (pad every 8 floats -> lane offsets 9*lane mod 32: conflict-free)
#define RT_MMAX 2312
#define RT_SIZE (RT_MMAX + (RT_MMAX >> 3) + 4)

// One scan step (all operands registers/smem). QC = current recips,
// QN = prefetch target for step kk+1. TFC/SFC current scalars (T=2k, 2*f[k-1]),
// TFN/SFN produced for next step.
#define SCAN_STEP(QC, QN, kk, TFC, SFC, TFN, SFN)                             \
do {                                                                          \
    TFN = TFC + 2.0f;                                                         \
    int kt = ((kk) < LSEQ) ? (kk) : (LSEQ - 1);                               \
    SFN = 2.0f * shf[kt];                                                     \
    int m0 = 2 * (kk) + 2 + mbase;                                            \
    _Pragma("unroll")                                                         \
    for (int e = 0; e < 8; e++) {                                             \
        int mm = m0 + e;                                                      \
        QN[e] = rtab[mm + (mm >> 3)];                                         \
    }                                                                         \
    float wt[8], rq[8], gg[8], uu[8];                                         \
    _Pragma("unroll")                                                         \
    for (int e = 0; e < 8; e++) {                                             \
        float a1 = (TFC - ip1[e]) * QC[e];                                    \
        rq[e] = rr[e] * QC[e];                                                \
        float s  = SFC - Sx[e];                                               \
        wt[e] = fmaf(a1, cc[e], rq[e] * s);                                   \
        uu[e] = rr[e] * wt[e];                                                \
        gg[e] = a1 + QC[e];                                                   \
    }                                                                         \
    float Aa[8], Bb[8];                                                       \
    Aa[0] = gg[0]; Bb[0] = uu[0];                                             \
    _Pragma("unroll")                                                         \
    for (int e = 1; e < 8; e++) {                                             \
        Aa[e] = Aa[e - 1] * gg[e];                                            \
        Bb[e] = fmaf(gg[e], Bb[e - 1], uu[e]);                                \
    }                                                                         \
    float A = Aa[7], B = Bb[7], Ao, Bo;                                       \
    Ao = __shfl_up_sync(0xffffffffu, A, 1);                                   \
    Bo = __shfl_up_sync(0xffffffffu, B, 1);                                   \
    if (lane >= 1)  { B = fmaf(A, Bo, B); A *= Ao; }                          \
    Ao = __shfl_up_sync(0xffffffffu, A, 2);                                   \
    Bo = __shfl_up_sync(0xffffffffu, B, 2);                                   \
    if (lane >= 2)  { B = fmaf(A, Bo, B); A *= Ao; }                          \
    Ao = __shfl_up_sync(0xffffffffu, A, 4);                                   \
    Bo = __shfl_up_sync(0xffffffffu, B, 4);                                   \
    if (lane >= 4)  { B = fmaf(A, Bo, B); A *= Ao; }                          \
    Ao = __shfl_up_sync(0xffffffffu, A, 8);                                   \
    Bo = __shfl_up_sync(0xffffffffu, B, 8);                                   \
    if (lane >= 8)  { B = fmaf(A, Bo, B); A *= Ao; }                          \
    Ao = __shfl_up_sync(0xffffffffu, A, 16);                                  \
    Bo = __shfl_up_sync(0xffffffffu, B, 16);                                  \
    if (lane >= 16) { B = fmaf(A, Bo, B); A *= Ao; }                          \
    float V = __shfl_up_sync(0xffffffffu, B, 1);                              \
    if (lane == 0) V = 0.0f;                                                  \
    Sx[0] = V;                                                                \
    cc[0] = fmaf(-rq[0], V, wt[0]);                                           \
    _Pragma("unroll")                                                         \
    for (int e = 1; e < 8; e++) {                                             \
        float Sn = fmaf(Aa[e - 1], V, Bb[e - 1]);                             \
        cc[e] = fmaf(-rq[e], Sn, wt[e]);                                      \
        Sx[e] = Sn;                                                           \
    }                                                                         \
    cptr[0] = make_float4(cc[0], cc[1], cc[2], cc[3]);                        \
    cptr[1] = make_float4(cc[4], cc[5], cc[6], cc[7]);                        \
    cptr += NDIM / 4;                                                         \
} while (0)

// ---------------------------------------------------------------------------
// Kernel 2 (fused): block 0 = sequential scan, blocks 1.. = GBT_A writer.
// ---------------------------------------------------------------------------
__global__ void __launch_bounds__(256) fused_kernel(
    const float* __restrict__ f,
    const float* __restrict__ init_state,
    float* __restrict__ out)
{
    if (blockIdx.x != 0) {
        // ----------------- GBT_A writer (validated) ------------------------
        int wb = blockIdx.x - 1;
        int k  = wb >> 3;
        int i0 = (wb & 7) * 32;
        int tx = threadIdx.x & 63;
        int ty = threadIdx.x >> 6;
        int jb = tx * 4;
        const float4 cv = *reinterpret_cast<const float4*>(&g_colv[k * NDIM + jb]);
        const int4   ev = *reinterpret_cast<const int4*>  (&g_Ej  [k * NDIM + jb]);
        float* base = out + (size_t)OFF_GBTA + (size_t)k * (NDIM * NDIM);
        #pragma unroll
        for (int rw = 0; rw < 8; rw++) {
            int i = i0 + ty + rw * 4;
            float rv = g_rowv[k * NDIM + i];
            int   Ei = g_Ei  [k * NDIM + i];
            float xd = g_xd  [k * NDIM + i];
            float4 o;
            o.x = (jb + 0 > i) ? 0.0f : ((jb + 0 == i) ? xd : rv * cv.x * pow2i(Ei - ev.x));
            o.y = (jb + 1 > i) ? 0.0f : ((jb + 1 == i) ? xd : rv * cv.y * pow2i(Ei - ev.y));
            o.z = (jb + 2 > i) ? 0.0f : ((jb + 2 == i) ? xd : rv * cv.z * pow2i(Ei - ev.z));
            o.w = (jb + 3 > i) ? 0.0f : ((jb + 3 == i) ? xd : rv * cv.w * pow2i(Ei - ev.w));
            *reinterpret_cast<float4*>(&base[(size_t)i * NDIM + jb]) = o;
        }
        return;
    }

    // --------------------- scan block ------------------------------------
    __shared__ float shf[LSEQ];
    __shared__ float rtab[RT_SIZE];
    for (int t = threadIdx.x; t < LSEQ; t += 256) shf[t] = f[t];
    for (int mth = threadIdx.x; mth < RT_MMAX; mth += 256) {
        float v = (mth == 0) ? 0.0f : (1.0f / (float)mth);
        rtab[mth + (mth >> 3)] = v;
    }
    __syncthreads();
    if (threadIdx.x >= 32) return;
    int lane = threadIdx.x;
    int mbase = lane * 8 + 1;

    float rr[8], ip1[8], cc[8], Sx[8];
    #pragma unroll
    for (int e = 0; e < 8; e++) {
        int i  = lane * 8 + e;
        rr[e]  = sqrtf(2.0f * (float)i + 1.0f);
        ip1[e] = (float)(i + 1);
        cc[e]  = init_state[i];
    }
    // Initial exclusive prefix of r_j * c_j
    {
        float lex[8]; float run = 0.0f;
        #pragma unroll
        for (int e = 0; e < 8; e++) { lex[e] = run; run = fmaf(rr[e], cc[e], run); }
        float tot = run;
        #pragma unroll
        for (int off = 1; off < 32; off <<= 1) {
            float v = __shfl_up_sync(0xffffffffu, tot, off);
            if (lane >= off) tot += v;
        }
        float carry = __shfl_up_sync(0xffffffffu, tot, 1);
        if (lane == 0) carry = 0.0f;
        #pragma unroll
        for (int e = 0; e < 8; e++) Sx[e] = carry + lex[e];
    }

    float4* cptr = reinterpret_cast<float4*>(out) + lane * 2;

    // Preload recips + scalars for step 1 (T=2, m = 2 + i + 1)
    float qA[8], qB[8];
    #pragma unroll
    for (int e = 0; e < 8; e++) {
        int mm = 2 + mbase + e;
        qA[e] = rtab[mm + (mm >> 3)];
    }
    float TfA = 2.0f, sfA = 2.0f * shf[0];
    float TfB, sfB;

    #pragma unroll 1
    for (int k = 1; k <= LSEQ; k += 2) {
        SCAN_STEP(qA, qB, k,     TfA, sfA, TfB, sfB);
        SCAN_STEP(qB, qA, k + 1, TfB, sfB, TfA, sfA);
    }
}

// ---------------------------------------------------------------------------
// Kernel 3: y_all[k] = sum_i c_all[k][i]
// ---------------------------------------------------------------------------
__global__ void y_kernel(const float* __restrict__ c_all, float* __restrict__ y_all)
{
    int row  = blockIdx.x * 8 + (threadIdx.x >> 5);
    int lane = threadIdx.x & 31;
    const float4* p = reinterpret_cast<const float4*>(c_all + (size_t)row * NDIM);
    float4 a = p[lane * 2], b = p[lane * 2 + 1];
    float s = ((a.x + a.y) + (a.z + a.w)) + ((b.x + b.y) + (b.z + b.w));
    #pragma unroll
    for (int off = 16; off >= 1; off >>= 1)
        s += __shfl_down_sync(0xffffffffu, s, off);
    if (lane == 0) y_all[row] = s;
}

extern "C" void kernel_launch(void* const* d_in, const int* in_sizes, int n_in,
                              void* d_out, int out_size)
{
    int fi = 0, ii = 1;
    if (n_in >= 4 && in_sizes[0] == NDIM * NDIM) { fi = 2; ii = 3; }
    const float* f    = (const float*)d_in[fi];
    const float* init = (const float*)d_in[ii];
    float* out = (float*)d_out;

    params_kernel<<<LSEQ, NDIM>>>(out + (size_t)OFF_GBTB);
    fused_kernel<<<1 + LSEQ * 8, 256>>>(f, init, out);
    y_kernel<<<LSEQ / 8, 256>>>(out, out + (size_t)OFF_Y);
}